// round 1
// baseline (speedup 1.0000x reference)
#include <cuda_runtime.h>
#include <math.h>

// Problem constants (match reference)
#define NU      50000
#define NI      50000
#define M_TOT   100000
#define IN_DIM  256
#define HID     128
#define OUT_DIM 64

// Scratch: projected features h (users then items), and message accumulators.
__device__ float g_h[(size_t)M_TOT * HID];    // 51.2 MB
__device__ float g_acc[(size_t)M_TOT * HID];  // 51.2 MB

__device__ __forceinline__ float elu1(float x) { return x > 0.f ? x : expm1f(x); }

__device__ __forceinline__ void red_add_v4(float* addr, float a, float b, float c, float d) {
    asm volatile("red.global.add.v4.f32 [%0], {%1,%2,%3,%4};"
                 :: "l"(addr), "f"(a), "f"(b), "f"(c), "f"(d) : "memory");
}

// ---------------------------------------------------------------------------
// Zero the accumulators (float4 stores)
// ---------------------------------------------------------------------------
__global__ void zero_kernel(float* __restrict__ p, long n4) {
    long i = (long)blockIdx.x * blockDim.x + threadIdx.x;
    long stride = (long)gridDim.x * blockDim.x;
    float4 z = make_float4(0.f, 0.f, 0.f, 0.f);
    for (; i < n4; i += stride) reinterpret_cast<float4*>(p)[i] = z;
}

// ---------------------------------------------------------------------------
// Projection: h = [x_user; x_item] @ W_proj + b_proj
// Tiled SGEMM: BM=128, BN=128(=HID), BK=16, 256 threads, 8x8 per thread.
// ---------------------------------------------------------------------------
__global__ __launch_bounds__(256) void proj_kernel(
    const float* __restrict__ xu, const float* __restrict__ xi,
    const float* __restrict__ W, const float* __restrict__ b,
    float* __restrict__ h)
{
    const int BM = 128, BK = 16;
    __shared__ float As[BK][BM + 4];   // transposed A tile
    __shared__ float Bs[BK][HID];

    const int m0  = blockIdx.x * BM;
    const int tid = threadIdx.x;
    const int tx  = tid & 15;   // column group (8 cols each)
    const int ty  = tid >> 4;   // row group (8 rows each)

    float acc[8][8];
#pragma unroll
    for (int i = 0; i < 8; i++)
#pragma unroll
        for (int j = 0; j < 8; j++) acc[i][j] = 0.f;

    for (int k0 = 0; k0 < IN_DIM; k0 += BK) {
        // Load A tile: 128 rows x 16 k, float4 along K, store transposed.
#pragma unroll
        for (int L = 0; L < 2; L++) {
            int idx = tid + L * 256;        // 0..511 float4 slots
            int row = idx >> 2;             // 0..127
            int kq  = (idx & 3) * 4;        // 0,4,8,12
            int gr  = m0 + row;
            float4 v = make_float4(0.f, 0.f, 0.f, 0.f);
            if (gr < M_TOT) {
                const float* src = (gr < NU) ? (xu + (size_t)gr * IN_DIM)
                                             : (xi + (size_t)(gr - NU) * IN_DIM);
                v = *reinterpret_cast<const float4*>(src + k0 + kq);
            }
            As[kq + 0][row] = v.x;
            As[kq + 1][row] = v.y;
            As[kq + 2][row] = v.z;
            As[kq + 3][row] = v.w;
        }
        // Load B tile: 16 k x 128 n, float4 along N.
#pragma unroll
        for (int L = 0; L < 2; L++) {
            int idx = tid + L * 256;        // 0..511 float4 slots
            int k   = idx >> 5;             // 0..15
            int n   = (idx & 31) * 4;       // 0..124
            float4 v = *reinterpret_cast<const float4*>(W + (size_t)(k0 + k) * HID + n);
            *reinterpret_cast<float4*>(&Bs[k][n]) = v;
        }
        __syncthreads();

#pragma unroll
        for (int k = 0; k < BK; k++) {
            float ra[8], rb[8];
            float4 a0 = *reinterpret_cast<const float4*>(&As[k][ty * 8]);
            float4 a1 = *reinterpret_cast<const float4*>(&As[k][ty * 8 + 4]);
            ra[0] = a0.x; ra[1] = a0.y; ra[2] = a0.z; ra[3] = a0.w;
            ra[4] = a1.x; ra[5] = a1.y; ra[6] = a1.z; ra[7] = a1.w;
            float4 b0 = *reinterpret_cast<const float4*>(&Bs[k][tx * 8]);
            float4 b1 = *reinterpret_cast<const float4*>(&Bs[k][tx * 8 + 4]);
            rb[0] = b0.x; rb[1] = b0.y; rb[2] = b0.z; rb[3] = b0.w;
            rb[4] = b1.x; rb[5] = b1.y; rb[6] = b1.z; rb[7] = b1.w;
#pragma unroll
            for (int i = 0; i < 8; i++)
#pragma unroll
                for (int j = 0; j < 8; j++)
                    acc[i][j] += ra[i] * rb[j];
        }
        __syncthreads();
    }

    // Epilogue: +bias, store to h
    float4 bv0 = *reinterpret_cast<const float4*>(b + tx * 8);
    float4 bv1 = *reinterpret_cast<const float4*>(b + tx * 8 + 4);
#pragma unroll
    for (int i = 0; i < 8; i++) {
        int gr = m0 + ty * 8 + i;
        if (gr < M_TOT) {
            float4 o0, o1;
            o0.x = acc[i][0] + bv0.x; o0.y = acc[i][1] + bv0.y;
            o0.z = acc[i][2] + bv0.z; o0.w = acc[i][3] + bv0.w;
            o1.x = acc[i][4] + bv1.x; o1.y = acc[i][5] + bv1.y;
            o1.z = acc[i][6] + bv1.z; o1.w = acc[i][7] + bv1.w;
            float* dst = h + (size_t)gr * HID + tx * 8;
            *reinterpret_cast<float4*>(dst)     = o0;
            *reinterpret_cast<float4*>(dst + 4) = o1;
        }
    }
}

// ---------------------------------------------------------------------------
// Edge message + scatter-add: one edge per warp, 4 floats per lane.
// acc[dst] += al * h_src[src] + ar * h_dst_tab[dst]
// ---------------------------------------------------------------------------
__global__ __launch_bounds__(256) void edge_kernel(
    const int* __restrict__ edges, int E,
    const float* __restrict__ hsrc, const float* __restrict__ hdst,
    const float* __restrict__ alp, const float* __restrict__ arp,
    float* __restrict__ accd)
{
    int gw = (int)((blockIdx.x * 256u + threadIdx.x) >> 5);
    if (gw >= E) return;
    int lane = threadIdx.x & 31;
    float al = __ldg(alp);
    float ar = __ldg(arp);
    int s = __ldg(&edges[2 * gw]);
    int d = __ldg(&edges[2 * gw + 1]);
    float4 hs = *reinterpret_cast<const float4*>(hsrc + (size_t)s * HID + lane * 4);
    float4 hd = *reinterpret_cast<const float4*>(hdst + (size_t)d * HID + lane * 4);
    red_add_v4(accd + (size_t)d * HID + lane * 4,
               al * hs.x + ar * hd.x,
               al * hs.y + ar * hd.y,
               al * hs.z + ar * hd.z,
               al * hs.w + ar * hd.w);
}

// ---------------------------------------------------------------------------
// User epilogue: out_u = elu(acc_u) @ W_out + b_out  (128 -> 64)
// 256 threads, 32 rows per block. W_out staged in SMEM (32 KB) + A tile (16 KB).
// ---------------------------------------------------------------------------
__global__ __launch_bounds__(256) void user_out_kernel(
    const float* __restrict__ acc_u, const float* __restrict__ Wout,
    const float* __restrict__ bout, float* __restrict__ out)
{
    __shared__ float Ws[HID][OUT_DIM];  // 32768 B
    __shared__ float sA[32][HID];       // 16384 B  (total = 48 KB exactly)

    const int tid = threadIdx.x;
    // Load W_out (8192 floats = 2048 float4)
#pragma unroll
    for (int L = 0; L < 8; L++) {
        int idx = tid + L * 256;
        reinterpret_cast<float4*>(&Ws[0][0])[idx] =
            reinterpret_cast<const float4*>(Wout)[idx];
    }
    const int r0 = blockIdx.x * 32;
    // Load 32 acc rows with elu applied (1024 float4)
#pragma unroll
    for (int L = 0; L < 4; L++) {
        int idx = tid + L * 256;
        int row = idx >> 5;     // 0..31
        int c4  = idx & 31;
        float4 v = make_float4(0.f, 0.f, 0.f, 0.f);
        int gr = r0 + row;
        if (gr < NU)
            v = reinterpret_cast<const float4*>(acc_u + (size_t)gr * HID)[c4];
        v.x = elu1(v.x); v.y = elu1(v.y); v.z = elu1(v.z); v.w = elu1(v.w);
        reinterpret_cast<float4*>(&sA[row][0])[c4] = v;
    }
    __syncthreads();

    const int row  = tid >> 3;        // 0..31
    const int cseg = (tid & 7) * 8;   // 0,8,...,56
    float o[8];
#pragma unroll
    for (int j = 0; j < 8; j++) o[j] = 0.f;

#pragma unroll
    for (int k = 0; k < HID; k += 4) {
        float4 a4 = reinterpret_cast<const float4*>(&sA[row][0])[k >> 2];
        float av[4] = {a4.x, a4.y, a4.z, a4.w};
#pragma unroll
        for (int q = 0; q < 4; q++) {
            float a = av[q];
#pragma unroll
            for (int j = 0; j < 8; j++)
                o[j] += a * Ws[k + q][cseg + j];
        }
    }

    int gr = r0 + row;
    if (gr < NU) {
        float4 bv0 = *reinterpret_cast<const float4*>(bout + cseg);
        float4 bv1 = *reinterpret_cast<const float4*>(bout + cseg + 4);
        float4 v0, v1;
        v0.x = o[0] + bv0.x; v0.y = o[1] + bv0.y; v0.z = o[2] + bv0.z; v0.w = o[3] + bv0.w;
        v1.x = o[4] + bv1.x; v1.y = o[5] + bv1.y; v1.z = o[6] + bv1.z; v1.w = o[7] + bv1.w;
        float* dst = out + (size_t)gr * OUT_DIM + cseg;
        *reinterpret_cast<float4*>(dst)     = v0;
        *reinterpret_cast<float4*>(dst + 4) = v1;
    }
}

// ---------------------------------------------------------------------------
// Item epilogue: out_i = elu(acc_i)   (elementwise, float4)
// ---------------------------------------------------------------------------
__global__ void item_out_kernel(const float* __restrict__ acc_i, float* __restrict__ out) {
    long n4 = (long)NI * HID / 4;
    long i = (long)blockIdx.x * blockDim.x + threadIdx.x;
    long stride = (long)gridDim.x * blockDim.x;
    for (; i < n4; i += stride) {
        float4 v = reinterpret_cast<const float4*>(acc_i)[i];
        v.x = elu1(v.x); v.y = elu1(v.y); v.z = elu1(v.z); v.w = elu1(v.w);
        reinterpret_cast<float4*>(out)[i] = v;
    }
}

// ---------------------------------------------------------------------------
// Launch
// ---------------------------------------------------------------------------
extern "C" void kernel_launch(void* const* d_in, const int* in_sizes, int n_in,
                              void* d_out, int out_size)
{
    const float* xu    = (const float*)d_in[0];
    const float* xi    = (const float*)d_in[1];
    const float* Wp    = (const float*)d_in[2];
    const float* bp    = (const float*)d_in[3];
    const float* al_uu = (const float*)d_in[4];
    const float* ar_uu = (const float*)d_in[5];
    const float* al_iu = (const float*)d_in[6];
    const float* ar_iu = (const float*)d_in[7];
    const float* al_ui = (const float*)d_in[8];
    const float* ar_ui = (const float*)d_in[9];
    const float* Wo    = (const float*)d_in[10];
    const float* bo    = (const float*)d_in[11];
    const int*   e_uu  = (const int*)d_in[12];
    const int*   e_iu  = (const int*)d_in[13];
    const int*   e_ui  = (const int*)d_in[14];
    const int E_uu = in_sizes[12] / 2;
    const int E_iu = in_sizes[13] / 2;
    const int E_ui = in_sizes[14] / 2;

    float* h;   cudaGetSymbolAddress((void**)&h,   g_h);
    float* acc; cudaGetSymbolAddress((void**)&acc, g_acc);
    float* h_u   = h;
    float* h_i   = h   + (size_t)NU * HID;
    float* acc_u = acc;
    float* acc_i = acc + (size_t)NU * HID;
    float* out_u = (float*)d_out;
    float* out_i = out_u + (size_t)NU * OUT_DIM;

    // 1) zero accumulators
    zero_kernel<<<2048, 256>>>(acc, (long)M_TOT * HID / 4);

    // 2) shared projection GEMM (users + items fused along M)
    proj_kernel<<<(M_TOT + 127) / 128, 256>>>(xu, xi, Wp, bp, h);

    // 3) edge scatter for the three relations (one edge per warp)
    edge_kernel<<<(E_uu * 32 + 255) / 256, 256>>>(e_uu, E_uu, h_u, h_u, al_uu, ar_uu, acc_u);
    edge_kernel<<<(E_iu * 32 + 255) / 256, 256>>>(e_iu, E_iu, h_i, h_u, al_iu, ar_iu, acc_u);
    edge_kernel<<<(E_ui * 32 + 255) / 256, 256>>>(e_ui, E_ui, h_u, h_i, al_ui, ar_ui, acc_i);

    // 4) epilogues
    user_out_kernel<<<(NU + 31) / 32, 256>>>(acc_u, Wo, bo, out_u);
    item_out_kernel<<<2048, 256>>>(acc_i, out_i);
}

// round 3
// speedup vs baseline: 1.4026x; 1.4026x over previous
#include <cuda_runtime.h>
#include <math.h>
#include <stdint.h>

// Problem constants
#define NU      50000
#define NI      50000
#define M_TOT   100000
#define IN_DIM  256
#define HID     128
#define OUT_DIM 64

// ---------------------------------------------------------------------------
// Device scratch (no allocations allowed)
// ---------------------------------------------------------------------------
__device__ float g_h[(size_t)M_TOT * HID];    // projected features (users then items)
__device__ float g_acc[(size_t)M_TOT * HID];  // message accumulators
__device__ int   g_deg[2 * NU + NI];          // [uu deg | iu deg | ui deg]

__device__ __forceinline__ float elu1(float x) { return x > 0.f ? x : expm1f(x); }

__device__ __forceinline__ void red_add_v4(float* addr, float a, float b, float c, float d) {
    asm volatile("red.global.add.v4.f32 [%0], {%1,%2,%3,%4};"
                 :: "l"(addr), "f"(a), "f"(b), "f"(c), "f"(d) : "memory");
}

__device__ __forceinline__ uint32_t smem_u32(const void* p) {
    uint32_t a;
    asm("{ .reg .u64 t; cvta.to.shared.u64 t, %1; cvt.u32.u64 %0, t; }" : "=r"(a) : "l"(p));
    return a;
}

__device__ __forceinline__ void cp_async16(uint32_t dst_smem, const void* src) {
    asm volatile("cp.async.cg.shared.global [%0], [%1], 16;"
                 :: "r"(dst_smem), "l"(src) : "memory");
}
#define CP_COMMIT() asm volatile("cp.async.commit_group;" ::: "memory")

__device__ __forceinline__ uint32_t f2tf32(float v) {
    uint32_t t;
    asm("cvt.rna.tf32.f32 %0, %1;" : "=r"(t) : "f"(v));
    return t;
}

__device__ __forceinline__ void mma_tf32(float& d0, float& d1, float& d2, float& d3,
                                         uint32_t a0, uint32_t a1, uint32_t a2, uint32_t a3,
                                         uint32_t b0, uint32_t b1) {
    asm volatile(
        "mma.sync.aligned.m16n8k8.row.col.f32.tf32.tf32.f32 "
        "{%0,%1,%2,%3}, {%4,%5,%6,%7}, {%8,%9}, {%0,%1,%2,%3};"
        : "+f"(d0), "+f"(d1), "+f"(d2), "+f"(d3)
        : "r"(a0), "r"(a1), "r"(a2), "r"(a3), "r"(b0), "r"(b1));
}

// ---------------------------------------------------------------------------
// Zero accumulators + degree counters in one pass
// ---------------------------------------------------------------------------
__global__ void zero_all_kernel(float4* __restrict__ acc4, long n4a,
                                int4* __restrict__ deg4, long n4d) {
    long i = (long)blockIdx.x * blockDim.x + threadIdx.x;
    long stride = (long)gridDim.x * blockDim.x;
    float4 z = make_float4(0.f, 0.f, 0.f, 0.f);
    int4 zi = make_int4(0, 0, 0, 0);
    long n = n4a + n4d;
    for (; i < n; i += stride) {
        if (i < n4a) acc4[i] = z;
        else deg4[i - n4a] = zi;
    }
}

// ---------------------------------------------------------------------------
// Degree counting: one thread per edge across the three relations
// deg layout: [0,NU)=uu, [NU,2NU)=iu, [2NU,2NU+NI)=ui
// ---------------------------------------------------------------------------
__global__ void count_deg_kernel(const int* __restrict__ e_uu, int Euu,
                                 const int* __restrict__ e_iu, int Eiu,
                                 const int* __restrict__ e_ui, int Eui,
                                 int* __restrict__ deg) {
    int e = blockIdx.x * 256 + threadIdx.x;
    int tot = Euu + Eiu + Eui;
    if (e >= tot) return;
    int d, off;
    if (e < Euu)            { d = __ldg(&e_uu[2 * e + 1]);               off = 0; }
    else if (e < Euu + Eiu) { d = __ldg(&e_iu[2 * (e - Euu) + 1]);       off = NU; }
    else                    { d = __ldg(&e_ui[2 * (e - Euu - Eiu) + 1]); off = 2 * NU; }
    atomicAdd(&deg[off + d], 1);
}

// ---------------------------------------------------------------------------
// Projection via mma.sync tf32: h = [x_user;x_item] @ W_proj + b_proj
// Block tile M=128 x N=128(=HID), K in 8 chunks of 32, cp.async double buffer.
// 8 warps in 2x4; warp tile 64x32; atoms m16n8k8.
// Smem: As [128][36] (conflict-free A frags), Bs [32][136] (conflict-free B frags)
// ---------------------------------------------------------------------------
#define KC       32
#define NCHUNK   (IN_DIM / KC)
#define AS_W     (128 * 36)          // words per A stage
#define BS_W     (32 * 136)          // words per B stage
#define STAGE_W  (AS_W + BS_W)
#define PROJ_SMEM (2 * STAGE_W * 4)  // 71680 bytes

__device__ __forceinline__ void proj_load_chunk(
    uint32_t sb, int stage,
    const float* __restrict__ xu, const float* __restrict__ xi,
    const float* __restrict__ W, int m0, int c, int tid)
{
    uint32_t sA = sb + (stage * STAGE_W) * 4;
    uint32_t sB = sA + AS_W * 4;
    // A: 128 rows x 32 k = 1024 float4 segments
#pragma unroll
    for (int L = 0; L < 4; L++) {
        int i = tid + L * 256;
        int row = i >> 3;            // 0..127
        int seg = i & 7;             // k quad: 0..7
        int gr = m0 + row;
        if (gr >= M_TOT) gr = M_TOT - 1;
        const float* src = (gr < NU) ? (xu + (size_t)gr * IN_DIM)
                                     : (xi + (size_t)(gr - NU) * IN_DIM);
        src += c * KC + seg * 4;
        cp_async16(sA + (row * 36 + seg * 4) * 4, src);
    }
    // B: 32 k-rows x 128 n = 1024 float4 segments (no transpose: W is [K][N])
#pragma unroll
    for (int L = 0; L < 4; L++) {
        int i = tid + L * 256;
        int k  = i >> 5;             // 0..31
        int n4 = i & 31;             // 0..31 (float4 along n)
        const float* src = W + (size_t)(c * KC + k) * HID + n4 * 4;
        cp_async16(sB + (k * 136 + n4 * 4) * 4, src);
    }
    CP_COMMIT();
}

__global__ __launch_bounds__(256, 2) void proj_mma_kernel(
    const float* __restrict__ xu, const float* __restrict__ xi,
    const float* __restrict__ W, const float* __restrict__ bias,
    float* __restrict__ h)
{
    extern __shared__ float smf[];
    uint32_t sb = smem_u32(smf);
    const int tid  = threadIdx.x;
    const int wid  = tid >> 5;
    const int lane = tid & 31;
    const int gid  = lane >> 2;        // group id 0..7
    const int tig  = lane & 3;         // thread in group 0..3
    const int wm   = wid >> 2;         // 0..1  -> 64 rows
    const int wn   = wid & 3;          // 0..3  -> 32 cols
    const int m0   = blockIdx.x * 128;

    float d[4][4][4];                  // [mtile][ntile][frag]
#pragma unroll
    for (int i = 0; i < 4; i++)
#pragma unroll
        for (int j = 0; j < 4; j++)
#pragma unroll
            for (int q = 0; q < 4; q++) d[i][j][q] = 0.f;

    proj_load_chunk(sb, 0, xu, xi, W, m0, 0, tid);
    proj_load_chunk(sb, 1, xu, xi, W, m0, 1, tid);

    for (int c = 0; c < NCHUNK; c++) {
        int s = c & 1;
        if (c < NCHUNK - 1) asm volatile("cp.async.wait_group 1;" ::: "memory");
        else                asm volatile("cp.async.wait_group 0;" ::: "memory");
        __syncthreads();

        const float* As = smf + s * STAGE_W;           // [128][36]
        const float* Bs = smf + s * STAGE_W + AS_W;    // [32][136]

#pragma unroll
        for (int ks = 0; ks < KC / 8; ks++) {
            // A fragments: 4 m-tiles
            uint32_t a[4][4];
#pragma unroll
            for (int mt = 0; mt < 4; mt++) {
                int mrow = wm * 64 + mt * 16 + gid;
                int kcol = ks * 8 + tig;
                a[mt][0] = f2tf32(As[(mrow)     * 36 + kcol]);
                a[mt][1] = f2tf32(As[(mrow + 8) * 36 + kcol]);
                a[mt][2] = f2tf32(As[(mrow)     * 36 + kcol + 4]);
                a[mt][3] = f2tf32(As[(mrow + 8) * 36 + kcol + 4]);
            }
            // B fragments: 4 n-tiles
            uint32_t b[4][2];
#pragma unroll
            for (int nt = 0; nt < 4; nt++) {
                int ncol = wn * 32 + nt * 8 + gid;
                int krow = ks * 8 + tig;
                b[nt][0] = f2tf32(Bs[(krow)     * 136 + ncol]);
                b[nt][1] = f2tf32(Bs[(krow + 4) * 136 + ncol]);
            }
#pragma unroll
            for (int mt = 0; mt < 4; mt++)
#pragma unroll
                for (int nt = 0; nt < 4; nt++)
                    mma_tf32(d[mt][nt][0], d[mt][nt][1], d[mt][nt][2], d[mt][nt][3],
                             a[mt][0], a[mt][1], a[mt][2], a[mt][3],
                             b[nt][0], b[nt][1]);
        }
        __syncthreads();
        if (c + 2 < NCHUNK)
            proj_load_chunk(sb, s, xu, xi, W, m0, c + 2, tid);
    }

    // Epilogue: bias + store.  c0,c1 -> (row gid, cols 2*tig..+1); c2,c3 -> row gid+8.
#pragma unroll
    for (int mt = 0; mt < 4; mt++) {
        int row0 = m0 + wm * 64 + mt * 16 + gid;
        int row1 = row0 + 8;
#pragma unroll
        for (int nt = 0; nt < 4; nt++) {
            int col = wn * 32 + nt * 8 + tig * 2;
            float2 bv = *reinterpret_cast<const float2*>(bias + col);
            if (row0 < M_TOT) {
                float2 v = make_float2(d[mt][nt][0] + bv.x, d[mt][nt][1] + bv.y);
                *reinterpret_cast<float2*>(h + (size_t)row0 * HID + col) = v;
            }
            if (row1 < M_TOT) {
                float2 v = make_float2(d[mt][nt][2] + bv.x, d[mt][nt][3] + bv.y);
                *reinterpret_cast<float2*>(h + (size_t)row1 * HID + col) = v;
            }
        }
    }
}

// ---------------------------------------------------------------------------
// Fused edge scatter (src term only): acc[d] += al * h_src[s]
// One edge per warp, 4 floats per lane.
// ---------------------------------------------------------------------------
__global__ __launch_bounds__(256) void edge_all_kernel(
    const int* __restrict__ e_uu, int Euu,
    const int* __restrict__ e_iu, int Eiu,
    const int* __restrict__ e_ui, int Eui,
    const float* __restrict__ h_u, const float* __restrict__ h_i,
    const float* __restrict__ al_uu, const float* __restrict__ al_iu,
    const float* __restrict__ al_ui,
    float* __restrict__ acc_u, float* __restrict__ acc_i)
{
    int gw = (int)((blockIdx.x * 256u + threadIdx.x) >> 5);
    int tot = Euu + Eiu + Eui;
    if (gw >= tot) return;
    int lane = threadIdx.x & 31;

    const int* ep;
    const float* hsrc;
    float* accd;
    float al;
    int e;
    if (gw < Euu)            { ep = e_uu; hsrc = h_u; accd = acc_u; al = __ldg(al_uu); e = gw; }
    else if (gw < Euu + Eiu) { ep = e_iu; hsrc = h_i; accd = acc_u; al = __ldg(al_iu); e = gw - Euu; }
    else                     { ep = e_ui; hsrc = h_u; accd = acc_i; al = __ldg(al_ui); e = gw - Euu - Eiu; }

    int s = __ldg(&ep[2 * e]);
    int d = __ldg(&ep[2 * e + 1]);
    float4 hs = *reinterpret_cast<const float4*>(hsrc + (size_t)s * HID + lane * 4);
    red_add_v4(accd + (size_t)d * HID + lane * 4,
               al * hs.x, al * hs.y, al * hs.z, al * hs.w);
}

// ---------------------------------------------------------------------------
// User epilogue: out_u = elu(acc_u + (ar_uu*deg_uu + ar_iu*deg_iu)*h_u) @ W_out + b_out
// ---------------------------------------------------------------------------
__global__ __launch_bounds__(256) void user_out_kernel(
    const float* __restrict__ acc_u, const float* __restrict__ h_u,
    const int* __restrict__ deg,
    const float* __restrict__ ar_uu_p, const float* __restrict__ ar_iu_p,
    const float* __restrict__ Wout, const float* __restrict__ bout,
    float* __restrict__ out)
{
    __shared__ float Ws[HID][OUT_DIM];  // 32 KB
    __shared__ float sA[32][HID];       // 16 KB

    const int tid = threadIdx.x;
    const float ar_uu = __ldg(ar_uu_p);
    const float ar_iu = __ldg(ar_iu_p);
#pragma unroll
    for (int L = 0; L < 8; L++) {
        int idx = tid + L * 256;
        reinterpret_cast<float4*>(&Ws[0][0])[idx] =
            reinterpret_cast<const float4*>(Wout)[idx];
    }
    const int r0 = blockIdx.x * 32;
#pragma unroll
    for (int L = 0; L < 4; L++) {
        int idx = tid + L * 256;
        int row = idx >> 5;
        int c4  = idx & 31;
        float4 v = make_float4(0.f, 0.f, 0.f, 0.f);
        int gr = r0 + row;
        if (gr < NU) {
            float sc = ar_uu * (float)__ldg(&deg[gr]) + ar_iu * (float)__ldg(&deg[NU + gr]);
            float4 a  = reinterpret_cast<const float4*>(acc_u + (size_t)gr * HID)[c4];
            float4 hh = reinterpret_cast<const float4*>(h_u   + (size_t)gr * HID)[c4];
            v.x = a.x + sc * hh.x; v.y = a.y + sc * hh.y;
            v.z = a.z + sc * hh.z; v.w = a.w + sc * hh.w;
        }
        v.x = elu1(v.x); v.y = elu1(v.y); v.z = elu1(v.z); v.w = elu1(v.w);
        reinterpret_cast<float4*>(&sA[row][0])[c4] = v;
    }
    __syncthreads();

    const int row  = tid >> 3;
    const int cseg = (tid & 7) * 8;
    float o[8];
#pragma unroll
    for (int j = 0; j < 8; j++) o[j] = 0.f;
#pragma unroll
    for (int k = 0; k < HID; k += 4) {
        float4 a4 = reinterpret_cast<const float4*>(&sA[row][0])[k >> 2];
        float av[4] = {a4.x, a4.y, a4.z, a4.w};
#pragma unroll
        for (int q = 0; q < 4; q++) {
            float a = av[q];
#pragma unroll
            for (int j = 0; j < 8; j++)
                o[j] += a * Ws[k + q][cseg + j];
        }
    }
    int gr = r0 + row;
    if (gr < NU) {
        float4 bv0 = *reinterpret_cast<const float4*>(bout + cseg);
        float4 bv1 = *reinterpret_cast<const float4*>(bout + cseg + 4);
        float4 v0, v1;
        v0.x = o[0] + bv0.x; v0.y = o[1] + bv0.y; v0.z = o[2] + bv0.z; v0.w = o[3] + bv0.w;
        v1.x = o[4] + bv1.x; v1.y = o[5] + bv1.y; v1.z = o[6] + bv1.z; v1.w = o[7] + bv1.w;
        float* dst = out + (size_t)gr * OUT_DIM + cseg;
        *reinterpret_cast<float4*>(dst)     = v0;
        *reinterpret_cast<float4*>(dst + 4) = v1;
    }
}

// ---------------------------------------------------------------------------
// Item epilogue: out_i = elu(acc_i + ar_ui*deg_ui*h_i)
// ---------------------------------------------------------------------------
__global__ void item_out_kernel(const float* __restrict__ acc_i,
                                const float* __restrict__ h_i,
                                const int* __restrict__ deg,
                                const float* __restrict__ ar_ui_p,
                                float* __restrict__ out) {
    const float ar_ui = __ldg(ar_ui_p);
    long n4 = (long)NI * HID / 4;
    long i = (long)blockIdx.x * blockDim.x + threadIdx.x;
    long stride = (long)gridDim.x * blockDim.x;
    for (; i < n4; i += stride) {
        long row = i >> 5;   // 32 float4 per row
        float sc = ar_ui * (float)__ldg(&deg[2 * NU + row]);
        float4 a  = reinterpret_cast<const float4*>(acc_i)[i];
        float4 hh = reinterpret_cast<const float4*>(h_i)[i];
        float4 v;
        v.x = elu1(a.x + sc * hh.x);
        v.y = elu1(a.y + sc * hh.y);
        v.z = elu1(a.z + sc * hh.z);
        v.w = elu1(a.w + sc * hh.w);
        reinterpret_cast<float4*>(out)[i] = v;
    }
}

// ---------------------------------------------------------------------------
// Launch
// ---------------------------------------------------------------------------
extern "C" void kernel_launch(void* const* d_in, const int* in_sizes, int n_in,
                              void* d_out, int out_size)
{
    const float* xu    = (const float*)d_in[0];
    const float* xi    = (const float*)d_in[1];
    const float* Wp    = (const float*)d_in[2];
    const float* bp    = (const float*)d_in[3];
    const float* al_uu = (const float*)d_in[4];
    const float* ar_uu = (const float*)d_in[5];
    const float* al_iu = (const float*)d_in[6];
    const float* ar_iu = (const float*)d_in[7];
    const float* al_ui = (const float*)d_in[8];
    const float* ar_ui = (const float*)d_in[9];
    const float* Wo    = (const float*)d_in[10];
    const float* bo    = (const float*)d_in[11];
    const int*   e_uu  = (const int*)d_in[12];
    const int*   e_iu  = (const int*)d_in[13];
    const int*   e_ui  = (const int*)d_in[14];
    const int E_uu = in_sizes[12] / 2;
    const int E_iu = in_sizes[13] / 2;
    const int E_ui = in_sizes[14] / 2;

    float* h;   cudaGetSymbolAddress((void**)&h,   g_h);
    float* acc; cudaGetSymbolAddress((void**)&acc, g_acc);
    int*   deg; cudaGetSymbolAddress((void**)&deg, g_deg);

    float* h_u   = h;
    float* h_i   = h   + (size_t)NU * HID;
    float* acc_u = acc;
    float* acc_i = acc + (size_t)NU * HID;
    float* out_u = (float*)d_out;
    float* out_i = out_u + (size_t)NU * OUT_DIM;

    cudaFuncSetAttribute(proj_mma_kernel,
                         cudaFuncAttributeMaxDynamicSharedMemorySize, PROJ_SMEM);

    // 1) zero acc + degrees
    zero_all_kernel<<<2048, 256>>>((float4*)acc, (long)M_TOT * HID / 4,
                                   (int4*)deg, (long)(2 * NU + NI) / 4);
    // 2) degree count
    count_deg_kernel<<<(E_uu + E_iu + E_ui + 255) / 256, 256>>>(
        e_uu, E_uu, e_iu, E_iu, e_ui, E_ui, deg);

    // 3) projection GEMM (mma.sync tf32)
    proj_mma_kernel<<<(M_TOT + 127) / 128, 256, PROJ_SMEM>>>(xu, xi, Wp, bp, h);

    // 4) fused edge scatter (src term only)
    int totE = E_uu + E_iu + E_ui;
    edge_all_kernel<<<(totE * 32 + 255) / 256, 256>>>(
        e_uu, E_uu, e_iu, E_iu, e_ui, E_ui,
        h_u, h_i, al_uu, al_iu, al_ui, acc_u, acc_i);

    // 5) epilogues (fold ar*deg*h term)
    user_out_kernel<<<(NU + 31) / 32, 256>>>(acc_u, h_u, deg, ar_uu, ar_iu, Wo, bo, out_u);
    item_out_kernel<<<2048, 256>>>(acc_i, h_i, deg, ar_ui, out_i);
}

// round 4
// speedup vs baseline: 1.5514x; 1.1060x over previous
#include <cuda_runtime.h>
#include <math.h>
#include <stdint.h>

// Problem constants
#define NU      50000
#define NI      50000
#define M_TOT   100000
#define IN_DIM  256
#define HID     128
#define OUT_DIM 64
#define NBIN    (NU + NI)        // 100000 destination bins (users then items)
#define BCAP    64               // bucket capacity per destination
#define OVF_CAP 8192

// ---------------------------------------------------------------------------
// Device scratch (no allocations allowed)
// ---------------------------------------------------------------------------
__device__ float    g_h[(size_t)M_TOT * HID];      // projected features
__device__ float    g_acc[(size_t)M_TOT * HID];    // per-destination message sums
__device__ int      g_cnt[NBIN];                   // per-bin edge counts
__device__ uint32_t g_bucket[(size_t)NBIN * BCAP]; // 25.6 MB bucket storage
__device__ int      g_ovfn;                        // overflow count
__device__ uint2    g_ovf[OVF_CAP];                // (bin, packed src) overflow

__device__ __forceinline__ float elu1(float x) { return x > 0.f ? x : expm1f(x); }

__device__ __forceinline__ void red_add_v4(float* addr, float a, float b, float c, float d) {
    asm volatile("red.global.add.v4.f32 [%0], {%1,%2,%3,%4};"
                 :: "l"(addr), "f"(a), "f"(b), "f"(c), "f"(d) : "memory");
}

__device__ __forceinline__ uint32_t smem_u32(const void* p) {
    uint32_t a;
    asm("{ .reg .u64 t; cvta.to.shared.u64 t, %1; cvt.u32.u64 %0, t; }" : "=r"(a) : "l"(p));
    return a;
}

__device__ __forceinline__ void cp_async16(uint32_t dst_smem, const void* src) {
    asm volatile("cp.async.cg.shared.global [%0], [%1], 16;"
                 :: "r"(dst_smem), "l"(src) : "memory");
}
#define CP_COMMIT() asm volatile("cp.async.commit_group;" ::: "memory")

__device__ __forceinline__ uint32_t f2tf32(float v) {
    uint32_t t;
    asm("cvt.rna.tf32.f32 %0, %1;" : "=r"(t) : "f"(v));
    return t;
}

__device__ __forceinline__ void mma_tf32(float& d0, float& d1, float& d2, float& d3,
                                         uint32_t a0, uint32_t a1, uint32_t a2, uint32_t a3,
                                         uint32_t b0, uint32_t b1) {
    asm volatile(
        "mma.sync.aligned.m16n8k8.row.col.f32.tf32.tf32.f32 "
        "{%0,%1,%2,%3}, {%4,%5,%6,%7}, {%8,%9}, {%0,%1,%2,%3};"
        : "+f"(d0), "+f"(d1), "+f"(d2), "+f"(d3)
        : "r"(a0), "r"(a1), "r"(a2), "r"(a3), "r"(b0), "r"(b1));
}

// ---------------------------------------------------------------------------
// Zero bin counters + overflow counter
// ---------------------------------------------------------------------------
__global__ void zero_cnt_kernel(int* __restrict__ cnt) {
    int i = blockIdx.x * blockDim.x + threadIdx.x;
    int stride = gridDim.x * blockDim.x;
    for (; i < NBIN; i += stride) cnt[i] = 0;
    if (blockIdx.x == 0 && threadIdx.x == 0) g_ovfn = 0;
}

// ---------------------------------------------------------------------------
// Fill destination buckets from the three edge lists.
// User bins [0,NU): uu edges (flag=0, src in h_u) + iu edges (flag=1, src in h_i)
// Item bins [NU,NBIN): ui edges (src in h_u)
// ---------------------------------------------------------------------------
__global__ void fill_bucket_kernel(const int2* __restrict__ e_uu, int Euu,
                                   const int2* __restrict__ e_iu, int Eiu,
                                   const int2* __restrict__ e_ui, int Eui) {
    int e = blockIdx.x * 256 + threadIdx.x;
    int tot = Euu + Eiu + Eui;
    if (e >= tot) return;
    int2 ed;
    int bin;
    uint32_t val;
    if (e < Euu) {
        ed = __ldg(&e_uu[e]);          bin = ed.y;      val = (uint32_t)ed.x;
    } else if (e < Euu + Eiu) {
        ed = __ldg(&e_iu[e - Euu]);    bin = ed.y;      val = (uint32_t)ed.x | 0x80000000u;
    } else {
        ed = __ldg(&e_ui[e - Euu - Eiu]); bin = NU + ed.y; val = (uint32_t)ed.x;
    }
    int pos = atomicAdd(&g_cnt[bin], 1);
    if (pos < BCAP) {
        g_bucket[(size_t)bin * BCAP + pos] = val;
    } else {
        int o = atomicAdd(&g_ovfn, 1);
        if (o < OVF_CAP) g_ovf[o] = make_uint2((uint32_t)bin, val);
    }
}

// ---------------------------------------------------------------------------
// Per-destination accumulation: one warp per bin.
// acc[bin] = sum_e al_e * h[src_e]  +  (sum_e ar_e) * h[bin]
// Writes every acc row exactly once (zeros for empty bins). Non-atomic.
// ---------------------------------------------------------------------------
__global__ __launch_bounds__(256) void bin_acc_kernel(
    const float* __restrict__ h,        // g_h (users then items)
    const float* __restrict__ al_uu, const float* __restrict__ ar_uu,
    const float* __restrict__ al_iu, const float* __restrict__ ar_iu,
    const float* __restrict__ al_ui, const float* __restrict__ ar_ui,
    float* __restrict__ acc)
{
    int bin = blockIdx.x * 8 + (threadIdx.x >> 5);
    if (bin >= NBIN) return;
    int lane = threadIdx.x & 31;
    bool is_item = bin >= NU;

    float aluu = __ldg(al_uu), aruu = __ldg(ar_uu);
    float aliu = __ldg(al_iu), ariu = __ldg(ar_iu);
    float alui = __ldg(al_ui), arui = __ldg(ar_ui);

    int n = __ldg(&g_cnt[bin]);
    if (n > BCAP) n = BCAP;

    const uint32_t* bk = g_bucket + (size_t)bin * BCAP;
    // h row for this destination (users: h row = bin; items: h row = bin too,
    // since g_h is [users | items] and item bin = NU + item_id).
    float4 hd = *reinterpret_cast<const float4*>(h + (size_t)bin * HID + lane * 4);

    float4 s4 = make_float4(0.f, 0.f, 0.f, 0.f);
    float coef = 0.f;

    // batch 1: entries 0..min(n,32)
    uint32_t my0 = (lane < n) ? __ldg(&bk[lane]) : 0u;
    int n1 = n < 32 ? n : 32;
    for (int j = 0; j < n1; j++) {
        uint32_t v = __shfl_sync(0xFFFFFFFFu, my0, j);
        uint32_t src = v & 0x7FFFFFFFu;
        float al, ar;
        size_t row;
        if (is_item) { al = alui; ar = arui; row = src; }               // src in h_u
        else if (v & 0x80000000u) { al = aliu; ar = ariu; row = (size_t)NU + src; } // h_i
        else { al = aluu; ar = aruu; row = src; }                       // h_u
        coef += ar;
        float4 hs = *reinterpret_cast<const float4*>(h + row * HID + lane * 4);
        s4.x += al * hs.x; s4.y += al * hs.y; s4.z += al * hs.z; s4.w += al * hs.w;
    }
    if (n > 32) {
        uint32_t my1 = (32 + lane < n) ? __ldg(&bk[32 + lane]) : 0u;
        int n2 = n - 32;
        for (int j = 0; j < n2; j++) {
            uint32_t v = __shfl_sync(0xFFFFFFFFu, my1, j);
            uint32_t src = v & 0x7FFFFFFFu;
            float al, ar;
            size_t row;
            if (is_item) { al = alui; ar = arui; row = src; }
            else if (v & 0x80000000u) { al = aliu; ar = ariu; row = (size_t)NU + src; }
            else { al = aluu; ar = aruu; row = src; }
            coef += ar;
            float4 hs = *reinterpret_cast<const float4*>(h + row * HID + lane * 4);
            s4.x += al * hs.x; s4.y += al * hs.y; s4.z += al * hs.z; s4.w += al * hs.w;
        }
    }
    s4.x += coef * hd.x; s4.y += coef * hd.y;
    s4.z += coef * hd.z; s4.w += coef * hd.w;
    *reinterpret_cast<float4*>(acc + (size_t)bin * HID + lane * 4) = s4;
}

// ---------------------------------------------------------------------------
// Overflow edges (expected 0): atomic RED on top of written acc rows.
// ---------------------------------------------------------------------------
__global__ __launch_bounds__(256) void ovf_kernel(
    const float* __restrict__ h,
    const float* __restrict__ al_uu, const float* __restrict__ ar_uu,
    const float* __restrict__ al_iu, const float* __restrict__ ar_iu,
    const float* __restrict__ al_ui, const float* __restrict__ ar_ui,
    float* __restrict__ acc)
{
    int nov = g_ovfn;
    if (nov > OVF_CAP) nov = OVF_CAP;
    int lane = threadIdx.x & 31;
    int gw = blockIdx.x * 8 + (threadIdx.x >> 5);
    int nwarps = gridDim.x * 8;
    for (int idx = gw; idx < nov; idx += nwarps) {
        uint2 ov = g_ovf[idx];
        int bin = (int)ov.x;
        uint32_t v = ov.y;
        uint32_t src = v & 0x7FFFFFFFu;
        bool is_item = bin >= NU;
        float al, ar;
        size_t row;
        if (is_item) { al = __ldg(al_ui); ar = __ldg(ar_ui); row = src; }
        else if (v & 0x80000000u) { al = __ldg(al_iu); ar = __ldg(ar_iu); row = (size_t)NU + src; }
        else { al = __ldg(al_uu); ar = __ldg(ar_uu); row = src; }
        float4 hs = *reinterpret_cast<const float4*>(h + row * HID + lane * 4);
        float4 hd = *reinterpret_cast<const float4*>(h + (size_t)bin * HID + lane * 4);
        red_add_v4(acc + (size_t)bin * HID + lane * 4,
                   al * hs.x + ar * hd.x, al * hs.y + ar * hd.y,
                   al * hs.z + ar * hd.z, al * hs.w + ar * hd.w);
    }
}

// ---------------------------------------------------------------------------
// Projection via mma.sync tf32: h = [x_user;x_item] @ W_proj + b_proj
// Block tile M=64 x N=128, K in 8 chunks of 32, cp.async double buffer.
// 8 warps in 2x4; warp tile 32x32; atoms m16n8k8. 3 CTAs/SM target.
// ---------------------------------------------------------------------------
#define KC       32
#define NCHUNK   (IN_DIM / KC)
#define BM       64
#define AS_W     (BM * 36)           // 2304 words per A stage
#define BS_W     (32 * 136)          // 4352 words per B stage
#define STAGE_W  (AS_W + BS_W)       // 6656
#define PROJ_SMEM (2 * STAGE_W * 4)  // 53248 bytes

__device__ __forceinline__ void proj_load_chunk(
    uint32_t sb, int stage,
    const float* __restrict__ xu, const float* __restrict__ xi,
    const float* __restrict__ W, int m0, int c, int tid)
{
    uint32_t sA = sb + (stage * STAGE_W) * 4;
    uint32_t sB = sA + AS_W * 4;
    // A: 64 rows x 32 k = 512 float4 segments
#pragma unroll
    for (int L = 0; L < 2; L++) {
        int i = tid + L * 256;
        int row = i >> 3;            // 0..63
        int seg = i & 7;             // k quad
        int gr = m0 + row;
        if (gr >= M_TOT) gr = M_TOT - 1;
        const float* src = (gr < NU) ? (xu + (size_t)gr * IN_DIM)
                                     : (xi + (size_t)(gr - NU) * IN_DIM);
        src += c * KC + seg * 4;
        cp_async16(sA + (row * 36 + seg * 4) * 4, src);
    }
    // B: 32 k-rows x 128 n = 1024 float4 segments
#pragma unroll
    for (int L = 0; L < 4; L++) {
        int i = tid + L * 256;
        int k  = i >> 5;             // 0..31
        int n4 = i & 31;
        const float* src = W + (size_t)(c * KC + k) * HID + n4 * 4;
        cp_async16(sB + (k * 136 + n4 * 4) * 4, src);
    }
    CP_COMMIT();
}

__global__ __launch_bounds__(256, 3) void proj_mma_kernel(
    const float* __restrict__ xu, const float* __restrict__ xi,
    const float* __restrict__ W, const float* __restrict__ bias,
    float* __restrict__ h)
{
    extern __shared__ float smf[];
    uint32_t sb = smem_u32(smf);
    const int tid  = threadIdx.x;
    const int wid  = tid >> 5;
    const int lane = tid & 31;
    const int gid  = lane >> 2;
    const int tig  = lane & 3;
    const int wm   = wid >> 2;         // 0..1 -> 32 rows each
    const int wn   = wid & 3;          // 0..3 -> 32 cols each
    const int m0   = blockIdx.x * BM;

    float d[2][4][4];
#pragma unroll
    for (int i = 0; i < 2; i++)
#pragma unroll
        for (int j = 0; j < 4; j++)
#pragma unroll
            for (int q = 0; q < 4; q++) d[i][j][q] = 0.f;

    proj_load_chunk(sb, 0, xu, xi, W, m0, 0, tid);
    proj_load_chunk(sb, 1, xu, xi, W, m0, 1, tid);

    for (int c = 0; c < NCHUNK; c++) {
        int s = c & 1;
        if (c < NCHUNK - 1) asm volatile("cp.async.wait_group 1;" ::: "memory");
        else                asm volatile("cp.async.wait_group 0;" ::: "memory");
        __syncthreads();

        const float* As = smf + s * STAGE_W;           // [64][36]
        const float* Bs = smf + s * STAGE_W + AS_W;    // [32][136]

#pragma unroll
        for (int ks = 0; ks < KC / 8; ks++) {
            uint32_t a[2][4];
#pragma unroll
            for (int mt = 0; mt < 2; mt++) {
                int mrow = wm * 32 + mt * 16 + gid;
                int kcol = ks * 8 + tig;
                a[mt][0] = f2tf32(As[(mrow)     * 36 + kcol]);
                a[mt][1] = f2tf32(As[(mrow + 8) * 36 + kcol]);
                a[mt][2] = f2tf32(As[(mrow)     * 36 + kcol + 4]);
                a[mt][3] = f2tf32(As[(mrow + 8) * 36 + kcol + 4]);
            }
            uint32_t b[4][2];
#pragma unroll
            for (int nt = 0; nt < 4; nt++) {
                int ncol = wn * 32 + nt * 8 + gid;
                int krow = ks * 8 + tig;
                b[nt][0] = f2tf32(Bs[(krow)     * 136 + ncol]);
                b[nt][1] = f2tf32(Bs[(krow + 4) * 136 + ncol]);
            }
#pragma unroll
            for (int mt = 0; mt < 2; mt++)
#pragma unroll
                for (int nt = 0; nt < 4; nt++)
                    mma_tf32(d[mt][nt][0], d[mt][nt][1], d[mt][nt][2], d[mt][nt][3],
                             a[mt][0], a[mt][1], a[mt][2], a[mt][3],
                             b[nt][0], b[nt][1]);
        }
        __syncthreads();
        if (c + 2 < NCHUNK)
            proj_load_chunk(sb, s, xu, xi, W, m0, c + 2, tid);
    }

#pragma unroll
    for (int mt = 0; mt < 2; mt++) {
        int row0 = m0 + wm * 32 + mt * 16 + gid;
        int row1 = row0 + 8;
#pragma unroll
        for (int nt = 0; nt < 4; nt++) {
            int col = wn * 32 + nt * 8 + tig * 2;
            float2 bv = *reinterpret_cast<const float2*>(bias + col);
            if (row0 < M_TOT) {
                float2 v = make_float2(d[mt][nt][0] + bv.x, d[mt][nt][1] + bv.y);
                *reinterpret_cast<float2*>(h + (size_t)row0 * HID + col) = v;
            }
            if (row1 < M_TOT) {
                float2 v = make_float2(d[mt][nt][2] + bv.x, d[mt][nt][3] + bv.y);
                *reinterpret_cast<float2*>(h + (size_t)row1 * HID + col) = v;
            }
        }
    }
}

// ---------------------------------------------------------------------------
// User epilogue: out_u = elu(acc_u) @ W_out + b_out
// ---------------------------------------------------------------------------
__global__ __launch_bounds__(256) void user_out_kernel(
    const float* __restrict__ acc_u,
    const float* __restrict__ Wout, const float* __restrict__ bout,
    float* __restrict__ out)
{
    __shared__ float Ws[HID][OUT_DIM];  // 32 KB
    __shared__ float sA[32][HID];       // 16 KB

    const int tid = threadIdx.x;
#pragma unroll
    for (int L = 0; L < 8; L++) {
        int idx = tid + L * 256;
        reinterpret_cast<float4*>(&Ws[0][0])[idx] =
            reinterpret_cast<const float4*>(Wout)[idx];
    }
    const int r0 = blockIdx.x * 32;
#pragma unroll
    for (int L = 0; L < 4; L++) {
        int idx = tid + L * 256;
        int row = idx >> 5;
        int c4  = idx & 31;
        float4 v = make_float4(0.f, 0.f, 0.f, 0.f);
        int gr = r0 + row;
        if (gr < NU)
            v = reinterpret_cast<const float4*>(acc_u + (size_t)gr * HID)[c4];
        v.x = elu1(v.x); v.y = elu1(v.y); v.z = elu1(v.z); v.w = elu1(v.w);
        reinterpret_cast<float4*>(&sA[row][0])[c4] = v;
    }
    __syncthreads();

    const int row  = tid >> 3;
    const int cseg = (tid & 7) * 8;
    float o[8];
#pragma unroll
    for (int j = 0; j < 8; j++) o[j] = 0.f;
#pragma unroll
    for (int k = 0; k < HID; k += 4) {
        float4 a4 = reinterpret_cast<const float4*>(&sA[row][0])[k >> 2];
        float av[4] = {a4.x, a4.y, a4.z, a4.w};
#pragma unroll
        for (int q = 0; q < 4; q++) {
            float a = av[q];
#pragma unroll
            for (int j = 0; j < 8; j++)
                o[j] += a * Ws[k + q][cseg + j];
        }
    }
    int gr = r0 + row;
    if (gr < NU) {
        float4 bv0 = *reinterpret_cast<const float4*>(bout + cseg);
        float4 bv1 = *reinterpret_cast<const float4*>(bout + cseg + 4);
        float4 v0, v1;
        v0.x = o[0] + bv0.x; v0.y = o[1] + bv0.y; v0.z = o[2] + bv0.z; v0.w = o[3] + bv0.w;
        v1.x = o[4] + bv1.x; v1.y = o[5] + bv1.y; v1.z = o[6] + bv1.z; v1.w = o[7] + bv1.w;
        float* dst = out + (size_t)gr * OUT_DIM + cseg;
        *reinterpret_cast<float4*>(dst)     = v0;
        *reinterpret_cast<float4*>(dst + 4) = v1;
    }
}

// ---------------------------------------------------------------------------
// Item epilogue: out_i = elu(acc_i)
// ---------------------------------------------------------------------------
__global__ void item_out_kernel(const float* __restrict__ acc_i, float* __restrict__ out) {
    long n4 = (long)NI * HID / 4;
    long i = (long)blockIdx.x * blockDim.x + threadIdx.x;
    long stride = (long)gridDim.x * blockDim.x;
    for (; i < n4; i += stride) {
        float4 a = reinterpret_cast<const float4*>(acc_i)[i];
        float4 v;
        v.x = elu1(a.x); v.y = elu1(a.y); v.z = elu1(a.z); v.w = elu1(a.w);
        reinterpret_cast<float4*>(out)[i] = v;
    }
}

// ---------------------------------------------------------------------------
// Launch
// ---------------------------------------------------------------------------
extern "C" void kernel_launch(void* const* d_in, const int* in_sizes, int n_in,
                              void* d_out, int out_size)
{
    const float* xu    = (const float*)d_in[0];
    const float* xi    = (const float*)d_in[1];
    const float* Wp    = (const float*)d_in[2];
    const float* bp    = (const float*)d_in[3];
    const float* al_uu = (const float*)d_in[4];
    const float* ar_uu = (const float*)d_in[5];
    const float* al_iu = (const float*)d_in[6];
    const float* ar_iu = (const float*)d_in[7];
    const float* al_ui = (const float*)d_in[8];
    const float* ar_ui = (const float*)d_in[9];
    const float* Wo    = (const float*)d_in[10];
    const float* bo    = (const float*)d_in[11];
    const int*   e_uu  = (const int*)d_in[12];
    const int*   e_iu  = (const int*)d_in[13];
    const int*   e_ui  = (const int*)d_in[14];
    const int E_uu = in_sizes[12] / 2;
    const int E_iu = in_sizes[13] / 2;
    const int E_ui = in_sizes[14] / 2;

    float* h;   cudaGetSymbolAddress((void**)&h,   g_h);
    float* acc; cudaGetSymbolAddress((void**)&acc, g_acc);
    int*   cnt; cudaGetSymbolAddress((void**)&cnt, g_cnt);

    float* acc_u = acc;
    float* acc_i = acc + (size_t)NU * HID;
    float* out_u = (float*)d_out;
    float* out_i = out_u + (size_t)NU * OUT_DIM;

    cudaFuncSetAttribute(proj_mma_kernel,
                         cudaFuncAttributeMaxDynamicSharedMemorySize, PROJ_SMEM);

    // 1) zero bin counters
    zero_cnt_kernel<<<128, 256>>>(cnt);

    // 2) bucket edges by destination
    int totE = E_uu + E_iu + E_ui;
    fill_bucket_kernel<<<(totE + 255) / 256, 256>>>(
        (const int2*)e_uu, E_uu, (const int2*)e_iu, E_iu, (const int2*)e_ui, E_ui);

    // 3) projection GEMM (mma.sync tf32, M=64 tiles)
    proj_mma_kernel<<<(M_TOT + BM - 1) / BM, 256, PROJ_SMEM>>>(xu, xi, Wp, bp, h);

    // 4) per-destination accumulation (non-atomic, one write per row)
    bin_acc_kernel<<<(NBIN + 7) / 8, 256>>>(
        h, al_uu, ar_uu, al_iu, ar_iu, al_ui, ar_ui, acc);

    // 5) overflow edges (expected none)
    ovf_kernel<<<64, 256>>>(h, al_uu, ar_uu, al_iu, ar_iu, al_ui, ar_ui, acc);

    // 6) epilogues
    user_out_kernel<<<(NU + 31) / 32, 256>>>(acc_u, Wo, bo, out_u);
    item_out_kernel<<<2048, 256>>>(acc_i, out_i);
}